// round 4
// baseline (speedup 1.0000x reference)
#include <cuda_runtime.h>
#include <math.h>

#define S_   8
#define B_   8
#define CIN  16
#define Hh   96
#define Ww   96
#define NF   64
#define Ll   5
#define HW   (Hh*Ww)

// Scratch (static device globals; allocation-free, graph-safe)
__device__ float g_i2h  [(size_t)S_*B_*192*HW];  // i2h conv for ALL steps (~226MB)
__device__ float g_f    [B_*32*HW];              // f = tanh(i2f + h2f), per step
__device__ float g_flows[B_*10*HW];              // flow fields, per step

// ---------------------------------------------------------------------------
// i2h: 3x3 conv, pad 1, CIN=16 -> 192, ALL timesteps in one launch.
// Block: 256 thr, 32x32 pixel tile, 8 output channels; thread = 4 px x 8 oc.
// ---------------------------------------------------------------------------
__global__ __launch_bounds__(256) void i2h_all_kernel(
    const float* __restrict__ x,      // [S*B, CIN, H, W]
    const float* __restrict__ w,      // [192, 16, 3, 3]
    const float* __restrict__ bias)   // [192]
{
    __shared__ float tile[34*34];
    __shared__ float wsh[8*9];
    const int tid  = threadIdx.x;
    const int col  = tid & 31, rowg = tid >> 5;      // rows rowg+8*i
    const int x0   = blockIdx.x*32, y0 = blockIdx.y*32;
    const int sb   = blockIdx.z / 24;                // s*B + b
    const int ocg  = (blockIdx.z % 24) * 8;

    float acc[8][4];
#pragma unroll
    for (int k = 0; k < 8; k++)
#pragma unroll
        for (int i = 0; i < 4; i++) acc[k][i] = 0.f;

    for (int ci = 0; ci < CIN; ci++) {
        const float* src = x + (size_t)(sb*CIN + ci)*HW;
        for (int i = tid; i < 34*34; i += 256) {
            int r = i / 34, c = i % 34;
            int gy = y0 - 1 + r, gx = x0 - 1 + c;
            tile[i] = (gy >= 0 && gy < Hh && gx >= 0 && gx < Ww) ? src[gy*Ww + gx] : 0.f;
        }
        if (tid < 72)
            wsh[tid] = w[((ocg + tid/9)*CIN + ci)*9 + tid%9];
        __syncthreads();
#pragma unroll
        for (int k = 0; k < 9; k++) {
            const int ky = k/3, kx = k%3;
            float wv[8];
#pragma unroll
            for (int kk = 0; kk < 8; kk++) wv[kk] = wsh[kk*9 + k];
#pragma unroll
            for (int i = 0; i < 4; i++) {
                float v = tile[(rowg + 8*i + ky)*34 + col + kx];
#pragma unroll
                for (int kk = 0; kk < 8; kk++) acc[kk][i] += v * wv[kk];
            }
        }
        __syncthreads();
    }
#pragma unroll
    for (int i = 0; i < 4; i++) {
        const int p = (y0 + rowg + 8*i)*Ww + x0 + col;
#pragma unroll
        for (int kk = 0; kk < 8; kk++)
            g_i2h[(size_t)(sb*192 + ocg + kk)*HW + p] = acc[kk][i] + bias[ocg + kk];
    }
}

// ---------------------------------------------------------------------------
// f = tanh(conv5x5(x, i2f) + conv5x5(h, h2f)), pad 2, 32 out channels.
// Block: 256 thr, 32x32 pixel tile, 8 output chans; thread = 4 px x 8 oc.
// nci = 16 at t=0 (h==0, skip h2f), else 80.
// ---------------------------------------------------------------------------
__global__ __launch_bounds__(256) void f_kernel(
    const float* __restrict__ xt,      // [B, CIN, H, W]
    const float* __restrict__ hprev,   // [B, NF, H, W] (may be null at t=0)
    const float* __restrict__ i2f_w,   // [32, 16, 5, 5]
    const float* __restrict__ i2f_b,
    const float* __restrict__ h2f_w,   // [32, 64, 5, 5]
    const float* __restrict__ h2f_b,
    int nci)
{
    __shared__ float tile[36*36];
    __shared__ float wsh[8*25];
    const int tid = threadIdx.x;
    const int col = tid & 31, rowg = tid >> 5;
    const int x0  = blockIdx.x*32, y0 = blockIdx.y*32;
    const int b   = blockIdx.z / 4;
    const int ocg = (blockIdx.z % 4) * 8;

    float acc[8][4];
#pragma unroll
    for (int k = 0; k < 8; k++)
#pragma unroll
        for (int i = 0; i < 4; i++) acc[k][i] = 0.f;

    for (int ci = 0; ci < nci; ci++) {
        const float* src = (ci < CIN) ? xt    + (size_t)(b*CIN + ci)*HW
                                      : hprev + (size_t)(b*NF + (ci - CIN))*HW;
        for (int i = tid; i < 36*36; i += 256) {
            int r = i / 36, c = i % 36;
            int gy = y0 - 2 + r, gx = x0 - 2 + c;
            tile[i] = (gy >= 0 && gy < Hh && gx >= 0 && gx < Ww) ? src[gy*Ww + gx] : 0.f;
        }
        if (tid < 200) {
            int oc = ocg + tid/25, k = tid%25;
            wsh[tid] = (ci < CIN) ? i2f_w[(oc*CIN + ci)*25 + k]
                                  : h2f_w[(oc*NF + (ci - CIN))*25 + k];
        }
        __syncthreads();
#pragma unroll
        for (int k = 0; k < 25; k++) {
            const int ky = k/5, kx = k%5;
            float wv[8];
#pragma unroll
            for (int kk = 0; kk < 8; kk++) wv[kk] = wsh[kk*25 + k];
#pragma unroll
            for (int i = 0; i < 4; i++) {
                float v = tile[(rowg + 8*i + ky)*36 + col + kx];
#pragma unroll
                for (int kk = 0; kk < 8; kk++) acc[kk][i] += v * wv[kk];
            }
        }
        __syncthreads();
    }
#pragma unroll
    for (int i = 0; i < 4; i++) {
        const int p = (y0 + rowg + 8*i)*Ww + x0 + col;
#pragma unroll
        for (int kk = 0; kk < 8; kk++)
            g_f[(size_t)(b*32 + ocg + kk)*HW + p] =
                tanhf(acc[kk][i] + i2f_b[ocg + kk] + h2f_b[ocg + kk]);
    }
}

// ---------------------------------------------------------------------------
// flows: 5x5 conv, pad 2, 32 -> 10 channels, from g_f.
// Block: 256 thr, 32x32 pixel tile; thread = 4 px x 10 oc (register-blocked).
// ---------------------------------------------------------------------------
__global__ __launch_bounds__(256) void flows_kernel(
    const float* __restrict__ w,      // [10, 32, 5, 5]
    const float* __restrict__ bias)   // [10]
{
    __shared__ float tile[36*36];
    __shared__ float wsh[10*25];
    const int tid = threadIdx.x;
    const int col = tid & 31, rowg = tid >> 5;
    const int x0  = blockIdx.x*32, y0 = blockIdx.y*32, b = blockIdx.z;

    float acc[10][4];
#pragma unroll
    for (int k = 0; k < 10; k++)
#pragma unroll
        for (int i = 0; i < 4; i++) acc[k][i] = 0.f;

    for (int ci = 0; ci < 32; ci++) {
        const float* src = g_f + (size_t)(b*32 + ci)*HW;
        for (int i = tid; i < 36*36; i += 256) {
            int r = i / 36, c = i % 36;
            int gy = y0 - 2 + r, gx = x0 - 2 + c;
            tile[i] = (gy >= 0 && gy < Hh && gx >= 0 && gx < Ww) ? src[gy*Ww + gx] : 0.f;
        }
        if (tid < 250)
            wsh[tid] = w[((tid/25)*32 + ci)*25 + tid%25];
        __syncthreads();
#pragma unroll
        for (int k = 0; k < 25; k++) {
            const int ky = k/5, kx = k%5;
            float wv[10];
#pragma unroll
            for (int kk = 0; kk < 10; kk++) wv[kk] = wsh[kk*25 + k];
#pragma unroll
            for (int i = 0; i < 4; i++) {
                float v = tile[(rowg + 8*i + ky)*36 + col + kx];
#pragma unroll
                for (int kk = 0; kk < 10; kk++) acc[kk][i] += v * wv[kk];
            }
        }
        __syncthreads();
    }
#pragma unroll
    for (int i = 0; i < 4; i++) {
        const int p = (y0 + rowg + 8*i)*Ww + x0 + col;
#pragma unroll
        for (int kk = 0; kk < 10; kk++)
            g_flows[(size_t)(b*10 + kk)*HW + p] = acc[kk][i] + bias[kk];
    }
}

// ---------------------------------------------------------------------------
// Fused: bilinear warp (L*NF=320 ch) -> ret 1x1 (320->192) -> GRU gates.
// Block = 64 consecutive pixels of one batch, 256 threads, dynamic smem.
// Dyn smem layout (floats):
//   [0, 10240)            s_warp: 160 channels x 64 px  (one half of 320)
//   [10240, 13328)        s_wt:   WCH x 193 weight chunk (padded)
//   [13328, 14608)        s_w00/01/10/11: 4 x 320 bilinear weights
//   [14608, 15888) (int)  s_ix0/ix1/iy0/iy1: 4 x 320 indices
// After GEMM, region reused to spill h2h[192][64].
// At t=0 (hzero): h2h == retb exactly; GEMM and gathers skipped entirely.
// ---------------------------------------------------------------------------
#define WCH 16
#define WG_DYN_FLOATS (10240 + WCH*193 + 4*320 + 4*320)
__global__ __launch_bounds__(256) void warp_gate_kernel(
    const float* __restrict__ hprev,  // [B, NF, H, W] (null at t=0)
    const float* __restrict__ i2h_t,  // [B, 192, H, W] for this step
    const float* __restrict__ retw,   // [192, 320]
    const float* __restrict__ retb,   // [192]
    float* __restrict__ hout,         // [B, NF, H, W]
    int hzero)
{
    extern __shared__ float dyn[];
    float* s_warp = dyn;                       // 10240
    float* s_wt   = dyn + 10240;               // 3088
    float* s_w00  = dyn + 10240 + WCH*193;     // 320 each
    float* s_w01  = s_w00 + 320;
    float* s_w10  = s_w01 + 320;
    float* s_w11  = s_w10 + 320;
    int*   s_ix0  = (int*)(s_w11 + 320);       // 320 each
    int*   s_ix1  = s_ix0 + 320;
    int*   s_iy0  = s_ix1 + 320;
    int*   s_iy1  = s_iy0 + 320;

    const int tid = threadIdx.x;
    const int px  = tid & 63;
    const int b   = blockIdx.y;
    const int p0  = blockIdx.x * 64;

    // GEMM thread mapping: 6 output chans (og) x 8 pixels (px8)
    const int og  = tid >> 3;          // 0..31  -> out chans og*6..og*6+5
    const int px8 = (tid & 7) * 8;     // 0,8,...,56
    float acc[6][8];
#pragma unroll
    for (int k = 0; k < 6; k++) {
        float bv = retb[og*6 + k];
#pragma unroll
        for (int i = 0; i < 8; i++) acc[k][i] = bv;
    }

    if (!hzero) {
        // Phase 0: bilinear sample coords per (level, pixel) — 5*64 entries
        for (int i = tid; i < Ll*64; i += 256) {
            const int l = i >> 6, lane = i & 63;
            const int pp = p0 + lane;
            const int yy = pp / Ww, xx = pp % Ww;
            float fx = g_flows[(size_t)((b*Ll + l)*2 + 0)*HW + pp];
            float fy = g_flows[(size_t)((b*Ll + l)*2 + 1)*HW + pp];
            float vx = (float)xx - fx, vy = (float)yy - fy;
            float gxn = 2.f*vx/(float)(Ww - 1) - 1.f;
            float gyn = 2.f*vy/(float)(Hh - 1) - 1.f;
            float pxf = ((gxn + 1.f)*(float)Ww - 1.f)*0.5f;
            float pyf = ((gyn + 1.f)*(float)Hh - 1.f)*0.5f;
            float x0f = floorf(pxf), y0f = floorf(pyf);
            int ix0 = (int)x0f, iy0 = (int)y0f, ix1 = ix0 + 1, iy1 = iy0 + 1;
            float wx1 = pxf - x0f, wx0 = 1.f - wx1;
            float wy1 = pyf - y0f, wy0 = 1.f - wy1;
            float vx0 = (ix0 >= 0 && ix0 < Ww) ? 1.f : 0.f;
            float vx1 = (ix1 >= 0 && ix1 < Ww) ? 1.f : 0.f;
            float vy0 = (iy0 >= 0 && iy0 < Hh) ? 1.f : 0.f;
            float vy1 = (iy1 >= 0 && iy1 < Hh) ? 1.f : 0.f;
            s_w00[i] = wy0*wx0*vy0*vx0;
            s_w01[i] = wy0*wx1*vy0*vx1;
            s_w10[i] = wy1*wx0*vy1*vx0;
            s_w11[i] = wy1*wx1*vy1*vx1;
            s_ix0[i] = min(max(ix0, 0), Ww - 1);
            s_ix1[i] = min(max(ix1, 0), Ww - 1);
            s_iy0[i] = min(max(iy0, 0), Hh - 1);
            s_iy1[i] = min(max(iy1, 0), Hh - 1);
        }
        __syncthreads();

        for (int half = 0; half < 2; half++) {
            const int jbase = half*160;
            // Phase 1: gather warped channels jbase..jbase+159 into shared
            const int jg = tid >> 6;                 // 0..3
            for (int jl = jg; jl < 160; jl += 4) {
                const int j = jbase + jl;
                const int l = j >> 6, c = j & 63;    // NF = 64
                const int ci = l*64 + px;
                const float* base = hprev + (size_t)(b*NF + c)*HW;
                const int r0 = s_iy0[ci]*Ww, r1 = s_iy1[ci]*Ww;
                s_warp[jl*64 + px] =
                      s_w00[ci]*base[r0 + s_ix0[ci]]
                    + s_w01[ci]*base[r0 + s_ix1[ci]]
                    + s_w10[ci]*base[r1 + s_ix0[ci]]
                    + s_w11[ci]*base[r1 + s_ix1[ci]];
            }
            __syncthreads();

            // Phase 2: accumulate; weights staged via smem in WCH-col chunks
            for (int jc = 0; jc < 160; jc += WCH) {
                for (int e = tid; e < WCH*192; e += 256) {
                    const int o = e >> 4, jj = e & (WCH - 1);
                    s_wt[jj*193 + o] = retw[o*320 + jbase + jc + jj];
                }
                __syncthreads();
#pragma unroll 4
                for (int jj = 0; jj < WCH; jj++) {
                    const float* wrow = &s_warp[(jc + jj)*64 + px8];
                    float4 wv0 = *(const float4*)(wrow);
                    float4 wv1 = *(const float4*)(wrow + 4);
#pragma unroll
                    for (int k = 0; k < 6; k++) {
                        float wt = s_wt[jj*193 + og*6 + k];
                        acc[k][0] += wt * wv0.x;  acc[k][1] += wt * wv0.y;
                        acc[k][2] += wt * wv0.z;  acc[k][3] += wt * wv0.w;
                        acc[k][4] += wt * wv1.x;  acc[k][5] += wt * wv1.y;
                        acc[k][6] += wt * wv1.z;  acc[k][7] += wt * wv1.w;
                    }
                }
                __syncthreads();
            }
        }
    }

    // Phase 2b: spill h2h[192][64] into dyn (all above is dead now)
    if (!hzero) { /* already synced after last chunk */ } else { __syncthreads(); }
#pragma unroll
    for (int k = 0; k < 6; k++) {
        const int o = og*6 + k;
#pragma unroll
        for (int i = 0; i < 8; i++) dyn[o*64 + px8 + i] = acc[k][i];
    }
    __syncthreads();

    // Phase 3: GRU gates — 64 ch x 64 px, 16 per thread
    const float* i2h = i2h_t + (size_t)(b*192)*HW;
    const int cg = tid >> 6;               // 0..3
    const int p  = p0 + px;
    for (int c = cg; c < NF; c += 4) {
        float hr = dyn[c*64 + px];
        float hu = dyn[(NF + c)*64 + px];
        float hm = dyn[(2*NF + c)*64 + px];
        float ir = i2h[(size_t)c*HW + p];
        float iu = i2h[(size_t)(NF + c)*HW + p];
        float im = i2h[(size_t)(2*NF + c)*HW + p];
        float r = 1.f / (1.f + expf(-(ir + hr)));
        float u = 1.f / (1.f + expf(-(iu + hu)));
        float m = tanhf(im + r*hm);
        float hp = hzero ? 0.f : hprev[(size_t)(b*NF + c)*HW + p];
        hout[(size_t)(b*NF + c)*HW + p] = u*hp + (1.f - u)*m;
    }
}

// ---------------------------------------------------------------------------
extern "C" void kernel_launch(void* const* d_in, const int* in_sizes, int n_in,
                              void* d_out, int out_size)
{
    const float* inputs  = (const float*)d_in[0];
    const float* i2h_w   = (const float*)d_in[1];
    const float* i2h_b   = (const float*)d_in[2];
    const float* i2f_w   = (const float*)d_in[3];
    const float* i2f_b   = (const float*)d_in[4];
    const float* h2f_w   = (const float*)d_in[5];
    const float* h2f_b   = (const float*)d_in[6];
    const float* flows_w = (const float*)d_in[7];
    const float* flows_b = (const float*)d_in[8];
    const float* ret_w   = (const float*)d_in[9];
    const float* ret_b   = (const float*)d_in[10];
    float* out = (float*)d_out;

    const size_t stepElems = (size_t)B_*NF*HW;
    const size_t i2hStep   = (size_t)B_*192*HW;
    const int    wgSmem    = WG_DYN_FLOATS * 4;   // ~63.5 KB

    float* g_i2h_p = nullptr;
    cudaGetSymbolAddress((void**)&g_i2h_p, g_i2h);
    cudaFuncSetAttribute(warp_gate_kernel,
                         cudaFuncAttributeMaxDynamicSharedMemorySize, wgSmem);

    // i2h for all timesteps in one launch (no recurrence dependence)
    i2h_all_kernel<<<dim3(3, 3, S_*B_*24), 256>>>(inputs, i2h_w, i2h_b);

    for (int t = 0; t < S_; t++) {
        const float* xt    = inputs + (size_t)t*B_*CIN*HW;
        const float* hprev = (t == 0) ? nullptr : out + (size_t)(t - 1)*stepElems;
        float*       ht    = out + (size_t)t*stepElems;
        const int    hz    = (t == 0) ? 1 : 0;

        f_kernel<<<dim3(3, 3, B_*4), 256>>>(xt, hprev, i2f_w, i2f_b,
                                            h2f_w, h2f_b, hz ? CIN : CIN + NF);
        flows_kernel<<<dim3(3, 3, B_), 256>>>(flows_w, flows_b);
        warp_gate_kernel<<<dim3(HW/64, B_), 256, wgSmem>>>(
            hprev, g_i2h_p + (size_t)t*i2hStep, ret_w, ret_b, ht, hz);
    }

    // h_last = outs[S-1], appended after outs if the harness expects it
    if ((size_t)out_size >= (size_t)S_*stepElems + stepElems) {
        cudaMemcpyAsync(out + (size_t)S_*stepElems,
                        out + (size_t)(S_ - 1)*stepElems,
                        stepElems*sizeof(float), cudaMemcpyDeviceToDevice);
    }
}

// round 13
// speedup vs baseline: 1.1402x; 1.1402x over previous
#include <cuda_runtime.h>
#include <math.h>

#define S_   8
#define B_   8
#define CIN  16
#define Hh   96
#define Ww   96
#define NF   64
#define Ll   5
#define HW   (Hh*Ww)

// Scratch (static device globals; allocation-free, graph-safe)
__device__ float g_i2h  [(size_t)S_*B_*192*HW];  // i2h conv for ALL steps (~226MB)
__device__ float g_fx   [(size_t)S_*B_*32*HW];   // x-part of f for ALL steps (~75MB)
__device__ float g_f    [B_*32*HW];              // f = tanh(fx + h-part), per step
__device__ float g_flows[B_*10*HW];              // flow fields, per step

// ---------------------------------------------------------------------------
// i2h: 3x3 conv, pad 1, CIN=16 -> 192, ALL timesteps in one launch.
// Block: 256 thr, 32x32 tile, 8 oc; thread = 4 px x 8 oc. 13824 CTAs.
// DOUBLE-BUFFERED: tile+weights for ci+1 load under ci's compute.
// ---------------------------------------------------------------------------
__global__ __launch_bounds__(256) void i2h_all_kernel(
    const float* __restrict__ x,      // [S*B, CIN, H, W]
    const float* __restrict__ w,      // [192, 16, 3, 3]
    const float* __restrict__ bias)   // [192]
{
    __shared__ float tile[2][34*34];
    __shared__ float wsh[2][8*9];
    const int tid  = threadIdx.x;
    const int col  = tid & 31, rowg = tid >> 5;
    const int x0   = blockIdx.x*32, y0 = blockIdx.y*32;
    const int sb   = blockIdx.z / 24;
    const int ocg  = (blockIdx.z % 24) * 8;

    auto load_ci = [&](int ci, int buf) {
        const float* src = x + (size_t)(sb*CIN + ci)*HW;
        for (int i = tid; i < 34*34; i += 256) {
            int r = i / 34, c = i % 34;
            int gy = y0 - 1 + r, gx = x0 - 1 + c;
            tile[buf][i] = (gy >= 0 && gy < Hh && gx >= 0 && gx < Ww)
                         ? src[gy*Ww + gx] : 0.f;
        }
        if (tid < 72)
            wsh[buf][tid] = w[((ocg + tid/9)*CIN + ci)*9 + tid%9];
    };

    float acc[8][4];
#pragma unroll
    for (int k = 0; k < 8; k++)
#pragma unroll
        for (int i = 0; i < 4; i++) acc[k][i] = 0.f;

    load_ci(0, 0);
    __syncthreads();

    for (int ci = 0; ci < CIN; ci++) {
        const int cur = ci & 1;
        if (ci + 1 < CIN) load_ci(ci + 1, cur ^ 1);
#pragma unroll
        for (int k = 0; k < 9; k++) {
            const int ky = k/3, kx = k%3;
            float wv[8];
#pragma unroll
            for (int kk = 0; kk < 8; kk++) wv[kk] = wsh[cur][kk*9 + k];
#pragma unroll
            for (int i = 0; i < 4; i++) {
                float v = tile[cur][(rowg + 8*i + ky)*34 + col + kx];
#pragma unroll
                for (int kk = 0; kk < 8; kk++) acc[kk][i] += v * wv[kk];
            }
        }
        __syncthreads();   // publish buf cur^1; protect buf cur for next load
    }
#pragma unroll
    for (int i = 0; i < 4; i++) {
        const int p = (y0 + rowg + 8*i)*Ww + x0 + col;
#pragma unroll
        for (int kk = 0; kk < 8; kk++)
            g_i2h[(size_t)(sb*192 + ocg + kk)*HW + p] = acc[kk][i] + bias[ocg + kk];
    }
}

// ---------------------------------------------------------------------------
// fx: x-part of f. 5x5 conv, pad 2, CIN=16 -> 32, ALL timesteps, i2f bias
// baked in. Block: 256 thr, 32x16 tile, 8 oc; thread = 2 px x 8 oc.
// Grid 3x6x(S*B*4) = 4608 CTAs. DOUBLE-BUFFERED.
// ---------------------------------------------------------------------------
__global__ __launch_bounds__(256) void fx_all_kernel(
    const float* __restrict__ x,      // [S*B, CIN, H, W]
    const float* __restrict__ i2f_w,  // [32, 16, 5, 5]
    const float* __restrict__ i2f_b)  // [32]
{
    __shared__ float tile[2][20*36];
    __shared__ float wsh[2][8*25];
    const int tid = threadIdx.x;
    const int col = tid & 31, rowg = tid >> 5;      // rows rowg, rowg+8
    const int x0  = blockIdx.x*32, y0 = blockIdx.y*16;
    const int sb  = blockIdx.z >> 2;
    const int ocg = (blockIdx.z & 3) * 8;

    auto load_ci = [&](int ci, int buf) {
        const float* src = x + (size_t)(sb*CIN + ci)*HW;
        for (int i = tid; i < 20*36; i += 256) {
            int r = i / 36, c = i % 36;
            int gy = y0 - 2 + r, gx = x0 - 2 + c;
            tile[buf][i] = (gy >= 0 && gy < Hh && gx >= 0 && gx < Ww)
                         ? src[gy*Ww + gx] : 0.f;
        }
        if (tid < 200) {
            int oc = ocg + tid/25, k = tid%25;
            wsh[buf][tid] = i2f_w[(oc*CIN + ci)*25 + k];
        }
    };

    float acc[8][2];
#pragma unroll
    for (int k = 0; k < 8; k++)
#pragma unroll
        for (int i = 0; i < 2; i++) acc[k][i] = 0.f;

    load_ci(0, 0);
    __syncthreads();

    for (int ci = 0; ci < CIN; ci++) {
        const int cur = ci & 1;
        if (ci + 1 < CIN) load_ci(ci + 1, cur ^ 1);
#pragma unroll
        for (int k = 0; k < 25; k++) {
            const int ky = k/5, kx = k%5;
            float wv[8];
#pragma unroll
            for (int kk = 0; kk < 8; kk++) wv[kk] = wsh[cur][kk*25 + k];
#pragma unroll
            for (int i = 0; i < 2; i++) {
                float v = tile[cur][(rowg + 8*i + ky)*36 + col + kx];
#pragma unroll
                for (int kk = 0; kk < 8; kk++) acc[kk][i] += v * wv[kk];
            }
        }
        __syncthreads();
    }
#pragma unroll
    for (int i = 0; i < 2; i++) {
        const int p = (y0 + rowg + 8*i)*Ww + x0 + col;
#pragma unroll
        for (int kk = 0; kk < 8; kk++)
            g_fx[(size_t)(sb*32 + ocg + kk)*HW + p] = acc[kk][i] + i2f_b[ocg + kk];
    }
}

// ---------------------------------------------------------------------------
// f = tanh(fx + conv5x5(h, h2f) + h2f_b), pad 2, 32 out channels.
// Per-step critical path loops ONLY the 64 h channels.
// Block: 256 thr, 32x16 tile, 8 oc; thread = 2 px x 8 oc. Grid 576 CTAs.
// DOUBLE-BUFFERED.
// ---------------------------------------------------------------------------
__global__ __launch_bounds__(256) void f_kernel(
    const float* __restrict__ hprev,   // [B, NF, H, W]
    const float* __restrict__ fx_t,    // [B, 32, H, W] for this step
    const float* __restrict__ h2f_w,   // [32, 64, 5, 5]
    const float* __restrict__ h2f_b)   // [32]
{
    __shared__ float tile[2][20*36];
    __shared__ float wsh[2][8*25];
    const int tid = threadIdx.x;
    const int col = tid & 31, rowg = tid >> 5;      // rows rowg, rowg+8
    const int x0  = blockIdx.x*32, y0 = blockIdx.y*16;
    const int b   = blockIdx.z >> 2;
    const int ocg = (blockIdx.z & 3) * 8;

    auto load_ci = [&](int ci, int buf) {
        const float* src = hprev + (size_t)(b*NF + ci)*HW;
        for (int i = tid; i < 20*36; i += 256) {
            int r = i / 36, c = i % 36;
            int gy = y0 - 2 + r, gx = x0 - 2 + c;
            tile[buf][i] = (gy >= 0 && gy < Hh && gx >= 0 && gx < Ww)
                         ? src[gy*Ww + gx] : 0.f;
        }
        if (tid < 200) {
            int oc = ocg + tid/25, k = tid%25;
            wsh[buf][tid] = h2f_w[(oc*NF + ci)*25 + k];
        }
    };

    float acc[8][2];
#pragma unroll
    for (int k = 0; k < 8; k++)
#pragma unroll
        for (int i = 0; i < 2; i++) acc[k][i] = 0.f;

    load_ci(0, 0);
    __syncthreads();

    for (int ci = 0; ci < NF; ci++) {
        const int cur = ci & 1;
        if (ci + 1 < NF) load_ci(ci + 1, cur ^ 1);
#pragma unroll
        for (int k = 0; k < 25; k++) {
            const int ky = k/5, kx = k%5;
            float wv[8];
#pragma unroll
            for (int kk = 0; kk < 8; kk++) wv[kk] = wsh[cur][kk*25 + k];
#pragma unroll
            for (int i = 0; i < 2; i++) {
                float v = tile[cur][(rowg + 8*i + ky)*36 + col + kx];
#pragma unroll
                for (int kk = 0; kk < 8; kk++) acc[kk][i] += v * wv[kk];
            }
        }
        __syncthreads();   // publish buf cur^1; protect buf cur for next load
    }
#pragma unroll
    for (int i = 0; i < 2; i++) {
        const int p = (y0 + rowg + 8*i)*Ww + x0 + col;
#pragma unroll
        for (int kk = 0; kk < 8; kk++)
            g_f[(size_t)(b*32 + ocg + kk)*HW + p] =
                tanhf(acc[kk][i] + fx_t[(size_t)(b*32 + ocg + kk)*HW + p]
                      + h2f_b[ocg + kk]);
    }
}

// ---------------------------------------------------------------------------
// flows: 5x5 conv, pad 2, 32 -> 10 channels, from g_f.
// Block: 256 thr, 16x16 tile; thread = 1 px x 10 oc. Grid 288 CTAs.
// DOUBLE-BUFFERED like f_kernel.
// ---------------------------------------------------------------------------
__global__ __launch_bounds__(256) void flows_kernel(
    const float* __restrict__ w,
    const float* __restrict__ bias)
{
    __shared__ float tile[2][20*20];
    __shared__ float wsh[2][10*25];
    const int tid = threadIdx.x;
    const int col = tid & 15, row = tid >> 4;       // 16x16 pixels
    const int x0  = blockIdx.x*16, y0 = blockIdx.y*16, b = blockIdx.z;

    auto load_ci = [&](int ci, int buf) {
        const float* src = g_f + (size_t)(b*32 + ci)*HW;
        for (int i = tid; i < 20*20; i += 256) {
            int r = i / 20, c = i % 20;
            int gy = y0 - 2 + r, gx = x0 - 2 + c;
            tile[buf][i] = (gy >= 0 && gy < Hh && gx >= 0 && gx < Ww)
                         ? src[gy*Ww + gx] : 0.f;
        }
        if (tid < 250)
            wsh[buf][tid] = w[((tid/25)*32 + ci)*25 + tid%25];
    };

    float acc[10];
#pragma unroll
    for (int k = 0; k < 10; k++) acc[k] = 0.f;

    load_ci(0, 0);
    __syncthreads();

    for (int ci = 0; ci < 32; ci++) {
        const int cur = ci & 1;
        if (ci + 1 < 32) load_ci(ci + 1, cur ^ 1);
#pragma unroll
        for (int k = 0; k < 25; k++) {
            const int ky = k/5, kx = k%5;
            float v = tile[cur][(row + ky)*20 + col + kx];
#pragma unroll
            for (int kk = 0; kk < 10; kk++) acc[kk] += v * wsh[cur][kk*25 + k];
        }
        __syncthreads();
    }
    const int p = (y0 + row)*Ww + x0 + col;
#pragma unroll
    for (int kk = 0; kk < 10; kk++)
        g_flows[(size_t)(b*10 + kk)*HW + p] = acc[kk] + bias[kk];
}

// ---------------------------------------------------------------------------
// Fused: bilinear warp (320 ch) -> ret 1x1 (320->192) -> GRU gates.
// Block = 64 pixels, 512 threads, __launch_bounds__(512,2).
// Gather phase: coords cached in registers per level (warp-uniform reload,
// <=3 reloads/half) and row offsets premultiplied by Ww in Phase 0.
// Weight chunks double-buffered + register-prefetched; 1 barrier/chunk.
// Phase 3 float4-vectorized.
// ---------------------------------------------------------------------------
#define WCH 16
#define WG_DYN_FLOATS (10240 + 2*WCH*193 + 4*320 + 4*320)
__global__ __launch_bounds__(512, 2) void warp_gate_kernel(
    const float* __restrict__ hprev,  // [B, NF, H, W] (null at t=0)
    const float* __restrict__ i2h_t,  // [B, 192, H, W] for this step
    const float* __restrict__ retw,   // [192, 320]
    const float* __restrict__ retb,   // [192]
    float* __restrict__ hout,         // [B, NF, H, W]
    int hzero)
{
    extern __shared__ float dyn[];
    float* s_warp = dyn;                         // 10240 floats
    float* s_wt   = dyn + 10240;                 // 2 x WCH*193 floats
    float* s_w00  = dyn + 10240 + 2*WCH*193;     // 320 each
    float* s_w01  = s_w00 + 320;
    float* s_w10  = s_w01 + 320;
    float* s_w11  = s_w10 + 320;
    int*   s_ix0  = (int*)(s_w11 + 320);
    int*   s_ix1  = s_ix0 + 320;
    int*   s_iy0  = s_ix1 + 320;                 // PREMULTIPLIED by Ww
    int*   s_iy1  = s_iy0 + 320;                 // PREMULTIPLIED by Ww

    const int tid = threadIdx.x;
    const int px  = tid & 63;
    const int b   = blockIdx.y;
    const int p0  = blockIdx.x * 64;

    // GEMM mapping: og (0..31) -> out chans og*6..og*6+5; px4 = 4 pixels
    const int og  = tid >> 4;
    const int px4 = (tid & 15) * 4;
    float acc[6][4];
#pragma unroll
    for (int k = 0; k < 6; k++) {
        float bv = retb[og*6 + k];
#pragma unroll
        for (int i = 0; i < 4; i++) acc[k][i] = bv;
    }

    // Weight-staging: 16*192 elems / 512 thr = 6 per thread
    const int wo = tid >> 4;           // rows wo + q*32
    const int wj = tid & 15;

    if (!hzero) {
        // Phase 0: bilinear coords for 5 levels x 64 px
        for (int i = tid; i < Ll*64; i += 512) {
            const int l = i >> 6, lane = i & 63;
            const int pp = p0 + lane;
            const int yy = pp / Ww, xx = pp % Ww;
            float fx = g_flows[(size_t)((b*Ll + l)*2 + 0)*HW + pp];
            float fy = g_flows[(size_t)((b*Ll + l)*2 + 1)*HW + pp];
            float vx = (float)xx - fx, vy = (float)yy - fy;
            float gxn = 2.f*vx/(float)(Ww - 1) - 1.f;
            float gyn = 2.f*vy/(float)(Hh - 1) - 1.f;
            float pxf = ((gxn + 1.f)*(float)Ww - 1.f)*0.5f;
            float pyf = ((gyn + 1.f)*(float)Hh - 1.f)*0.5f;
            float x0f = floorf(pxf), y0f = floorf(pyf);
            int ix0 = (int)x0f, iy0 = (int)y0f, ix1 = ix0 + 1, iy1 = iy0 + 1;
            float wx1 = pxf - x0f, wx0 = 1.f - wx1;
            float wy1 = pyf - y0f, wy0 = 1.f - wy1;
            float vx0 = (ix0 >= 0 && ix0 < Ww) ? 1.f : 0.f;
            float vx1 = (ix1 >= 0 && ix1 < Ww) ? 1.f : 0.f;
            float vy0 = (iy0 >= 0 && iy0 < Hh) ? 1.f : 0.f;
            float vy1 = (iy1 >= 0 && iy1 < Hh) ? 1.f : 0.f;
            s_w00[i] = wy0*wx0*vy0*vx0;
            s_w01[i] = wy0*wx1*vy0*vx1;
            s_w10[i] = wy1*wx0*vy1*vx0;
            s_w11[i] = wy1*wx1*vy1*vx1;
            s_ix0[i] = min(max(ix0, 0), Ww - 1);
            s_ix1[i] = min(max(ix1, 0), Ww - 1);
            s_iy0[i] = min(max(iy0, 0), Hh - 1) * Ww;
            s_iy1[i] = min(max(iy1, 0), Hh - 1) * Ww;
        }

        float wreg[6];
#pragma unroll
        for (int q = 0; q < 6; q++)            // prefetch chunk 0
            wreg[q] = retw[(wo + q*32)*320 + wj];

        for (int half = 0; half < 2; half++) {
            const int jbase = half*160;
            // Phase 1: gather warped channels jbase..jbase+159 into shared.
            if (half == 0) __syncthreads();    // coords visible
            const int jg = tid >> 6;           // 0..7
            {
                int   lprev = -1;
                float w00 = 0.f, w01 = 0.f, w10 = 0.f, w11 = 0.f;
                int   cix0 = 0, cix1 = 0, cr0 = 0, cr1 = 0;
                for (int jl = jg; jl < 160; jl += 8) {
                    const int j = jbase + jl;
                    const int l = j >> 6;          // warp-uniform (jg fixed)
                    if (l != lprev) {
                        const int ci = l*64 + px;
                        w00 = s_w00[ci]; w01 = s_w01[ci];
                        w10 = s_w10[ci]; w11 = s_w11[ci];
                        cix0 = s_ix0[ci]; cix1 = s_ix1[ci];
                        cr0  = s_iy0[ci]; cr1  = s_iy1[ci];
                        lprev = l;
                    }
                    const int c = j & 63;          // NF = 64
                    const float* base = hprev + (size_t)(b*NF + c)*HW;
                    s_warp[jl*64 + px] =
                          w00*base[cr0 + cix0] + w01*base[cr0 + cix1]
                        + w10*base[cr1 + cix0] + w11*base[cr1 + cix1];
                }
            }
            if (half == 0) {
                __syncthreads();               // gather 0 visible
#pragma unroll
                for (int q = 0; q < 6; q++)    // STS chunk 0 -> buf 0
                    s_wt[wj*193 + wo + q*32] = wreg[q];
#pragma unroll
                for (int q = 0; q < 6; q++)    // prefetch chunk 1
                    wreg[q] = retw[(wo + q*32)*320 + 16 + wj];
            }

            for (int i = 0; i < 10; i++) {
                const int g = half*10 + i;
                __syncthreads();   // publish chunk g (+gather, half 1, i=0);
                                   // retire reads of buf (g+1)&1 (iter g-1)
                const int gn = g + 1;
                if (gn < 20) {
                    float* dst = s_wt + (gn & 1)*(WCH*193);
#pragma unroll
                    for (int q = 0; q < 6; q++)
                        dst[wj*193 + wo + q*32] = wreg[q];
                    if (gn + 1 < 20) {
#pragma unroll
                        for (int q = 0; q < 6; q++)
                            wreg[q] = retw[(wo + q*32)*320 + (gn+1)*16 + wj];
                    }
                }
                const float* wt_buf = s_wt + (g & 1)*(WCH*193);
                const int jc = i*16;
#pragma unroll 4
                for (int jj = 0; jj < WCH; jj++) {
                    float4 wv = *(const float4*)&s_warp[(jc + jj)*64 + px4];
#pragma unroll
                    for (int k = 0; k < 6; k++) {
                        float wt = wt_buf[jj*193 + og*6 + k];
                        acc[k][0] += wt * wv.x;
                        acc[k][1] += wt * wv.y;
                        acc[k][2] += wt * wv.z;
                        acc[k][3] += wt * wv.w;
                    }
                }
            }
            __syncthreads();   // s_warp reads done before next gather / spill
        }
    } else {
        __syncthreads();
    }

    // Phase 2b: spill h2h[192][64] into dyn (everything above is dead)
#pragma unroll
    for (int k = 0; k < 6; k++) {
        const int o = og*6 + k;
#pragma unroll
        for (int i = 0; i < 4; i++) dyn[o*64 + px4 + i] = acc[k][i];
    }
    __syncthreads();

    // Phase 3: GRU gates — float4-vectorized. Thread = 2 channels x 4 px.
    // All offsets 16B-aligned: HW%4==0, p0%4==0, px4%4==0.
    const float* i2h = i2h_t + (size_t)(b*192)*HW;
    const int p4 = p0 + px4;
#pragma unroll
    for (int q = 0; q < 2; q++) {
        const int c = og + q*32;
        float4 hr = *(const float4*)&dyn[(size_t)(c       )*64 + px4];
        float4 hu = *(const float4*)&dyn[(size_t)(NF   + c)*64 + px4];
        float4 hm = *(const float4*)&dyn[(size_t)(2*NF + c)*64 + px4];
        float4 ir = *(const float4*)&i2h[(size_t)(c       )*HW + p4];
        float4 iu = *(const float4*)&i2h[(size_t)(NF   + c)*HW + p4];
        float4 im = *(const float4*)&i2h[(size_t)(2*NF + c)*HW + p4];
        float4 hp = hzero ? make_float4(0.f, 0.f, 0.f, 0.f)
                          : *(const float4*)&hprev[(size_t)(b*NF + c)*HW + p4];
        float4 o;
        {
            float r = 1.f/(1.f + expf(-(ir.x + hr.x)));
            float u = 1.f/(1.f + expf(-(iu.x + hu.x)));
            float m = tanhf(im.x + r*hm.x);
            o.x = u*hp.x + (1.f - u)*m;
        }
        {
            float r = 1.f/(1.f + expf(-(ir.y + hr.y)));
            float u = 1.f/(1.f + expf(-(iu.y + hu.y)));
            float m = tanhf(im.y + r*hm.y);
            o.y = u*hp.y + (1.f - u)*m;
        }
        {
            float r = 1.f/(1.f + expf(-(ir.z + hr.z)));
            float u = 1.f/(1.f + expf(-(iu.z + hu.z)));
            float m = tanhf(im.z + r*hm.z);
            o.z = u*hp.z + (1.f - u)*m;
        }
        {
            float r = 1.f/(1.f + expf(-(ir.w + hr.w)));
            float u = 1.f/(1.f + expf(-(iu.w + hu.w)));
            float m = tanhf(im.w + r*hm.w);
            o.w = u*hp.w + (1.f - u)*m;
        }
        *(float4*)&hout[(size_t)(b*NF + c)*HW + p4] = o;
    }
}

// ---------------------------------------------------------------------------
extern "C" void kernel_launch(void* const* d_in, const int* in_sizes, int n_in,
                              void* d_out, int out_size)
{
    const float* inputs  = (const float*)d_in[0];
    const float* i2h_w   = (const float*)d_in[1];
    const float* i2h_b   = (const float*)d_in[2];
    const float* i2f_w   = (const float*)d_in[3];
    const float* i2f_b   = (const float*)d_in[4];
    const float* h2f_w   = (const float*)d_in[5];
    const float* h2f_b   = (const float*)d_in[6];
    const float* flows_w = (const float*)d_in[7];
    const float* flows_b = (const float*)d_in[8];
    const float* ret_w   = (const float*)d_in[9];
    const float* ret_b   = (const float*)d_in[10];
    float* out = (float*)d_out;

    const size_t stepElems = (size_t)B_*NF*HW;
    const size_t i2hStep   = (size_t)B_*192*HW;
    const size_t fxStep    = (size_t)B_*32*HW;
    const int    wgSmem    = WG_DYN_FLOATS * 4;   // ~75.9 KB

    float* g_i2h_p = nullptr;
    float* g_fx_p  = nullptr;
    cudaGetSymbolAddress((void**)&g_i2h_p, g_i2h);
    cudaGetSymbolAddress((void**)&g_fx_p,  g_fx);
    cudaFuncSetAttribute(warp_gate_kernel,
                         cudaFuncAttributeMaxDynamicSharedMemorySize, wgSmem);

    // Prelude: all-timestep precomputation (no recurrence dependence)
    i2h_all_kernel<<<dim3(3, 3, S_*B_*24), 256>>>(inputs, i2h_w, i2h_b);
    fx_all_kernel <<<dim3(3, 6, S_*B_*4),  256>>>(inputs, i2f_w, i2f_b);

    for (int t = 0; t < S_; t++) {
        const float* hprev = (t == 0) ? nullptr : out + (size_t)(t - 1)*stepElems;
        float*       ht    = out + (size_t)t*stepElems;
        const int    hz    = (t == 0) ? 1 : 0;

        // t=0: h==0 -> warped h == 0 -> h2h == retb. f and flows feed ONLY the
        // warp path, so both launches are dead work at t=0 and are skipped.
        if (!hz) {
            f_kernel<<<dim3(3, 6, B_*4), 256>>>(hprev, g_fx_p + (size_t)t*fxStep,
                                                h2f_w, h2f_b);
            flows_kernel<<<dim3(6, 6, B_), 256>>>(flows_w, flows_b);
        }
        warp_gate_kernel<<<dim3(HW/64, B_), 512, wgSmem>>>(
            hprev, g_i2h_p + (size_t)t*i2hStep, ret_w, ret_b, ht, hz);
    }

    // h_last = outs[S-1], appended after outs if the harness expects it
    if ((size_t)out_size >= (size_t)S_*stepElems + stepElems) {
        cudaMemcpyAsync(out + (size_t)S_*stepElems,
                        out + (size_t)(S_ - 1)*stepElems,
                        stepElems*sizeof(float), cudaMemcpyDeviceToDevice);
    }
}